// round 16
// baseline (speedup 1.0000x reference)
#include <cuda_runtime.h>
#include <cuda_fp16.h>
#include <cstdint>

// Problem constants
#define NN   2048
#define BB   64
#define CC   64
#define ED   10
#define BC   4096
#define KCH  3

// ---------------- scratch ------------------------------------------------------
__device__ float  g_Et   [(size_t)ED * NN];   // E^T fp32 [d][m]
__device__ __half g_Ah   [(size_t)NN * NN];   // softmax(relu(E E^T)), fp16
__device__ __half g_xTTh [(size_t)BC * NN];   // xTT[b*64+c][n], fp16 (GEMM1 B operand)
__device__ __half g_xh   [(size_t)NN * BC];   // x as [n][b*64+c], fp16 (final_tc seg0)
__device__ __half g_Xg1h [(size_t)NN * BC];   // A @ xT, fp16 [n][bc]
__device__ __half g_Xg1T [(size_t)BC * NN];   // Xg1^T fp16 (GEMM2 B operand)
__device__ __half g_Xg2ph[(size_t)NN * BC];   // 2 A @ Xg1, fp16 [n][bc]
__device__ __half g_Wph  [(size_t)ED * KCH * CC * CC]; // Wp [d][k][o][i], slot0 folded
__device__ __half g_WhT  [(size_t)NN * KCH * CC * CC]; // per-node W^T [n][k][o][i]

// ---------------- helpers ------------------------------------------------
__device__ __forceinline__ uint32_t smem_u32(const void* p) {
    uint32_t a;
    asm("{ .reg .u64 t; cvta.to.shared.u64 t, %1; cvt.u32.u64 %0, t; }" : "=r"(a) : "l"(p));
    return a;
}
__device__ __forceinline__ void cp16(uint32_t dst, const void* src) {
    asm volatile("cp.async.cg.shared.global [%0], [%1], 16;" :: "r"(dst), "l"(src) : "memory");
}
__device__ __forceinline__ void mma16(float* d, const uint32_t* a, const uint32_t* b) {
    asm volatile("mma.sync.aligned.m16n8k16.row.col.f32.f16.f16.f32 "
        "{%0,%1,%2,%3}, {%4,%5,%6,%7}, {%8,%9}, {%0,%1,%2,%3};"
        : "+f"(d[0]), "+f"(d[1]), "+f"(d[2]), "+f"(d[3])
        : "r"(a[0]), "r"(a[1]), "r"(a[2]), "r"(a[3]), "r"(b[0]), "r"(b[1]));
}
__device__ __forceinline__ void ldmat4(uint32_t* r, uint32_t addr) {
    asm volatile("ldmatrix.sync.aligned.m8n8.x4.shared.b16 {%0,%1,%2,%3}, [%4];"
        : "=r"(r[0]), "=r"(r[1]), "=r"(r[2]), "=r"(r[3]) : "r"(addr));
}

// ---------------- fp16 mma.sync GEMM: Ch = fp16(alpha * Aop @ Bop^T) ---------
// CTA tile 128x128, 4 warps x (64x64) warp tiles, K-chunk 64, 3-stage cp.async
// pipeline, ldmatrix fragment feeds.  blockDim = 128.
// by0: M-block offset.  If Ct != null, also writes fp16 transposed tile to Ct.
__global__ __launch_bounds__(128, 2)
void gemm_mma(const __half* __restrict__ Aop, const __half* __restrict__ Bop,
              __half* __restrict__ Ch, int ldcN, float alpha,
              __half* __restrict__ Ct, int by0)
{
    extern __shared__ char smem[];
    uint32_t sbase = smem_u32(smem);

    int tid = threadIdx.x, wid = tid >> 5, lid = tid & 31;
    int m0 = (blockIdx.y + by0) * 128, n0 = blockIdx.x * 128;

    int ldr = tid >> 3, ldc8 = tid & 7;
    uint32_t swz_ld = (uint32_t)(ldr * 128 + ((ldc8 * 16) ^ ((ldr & 7) * 16)));
    const __half* ga = Aop + (size_t)(m0 + ldr) * NN + ldc8 * 8;
    const __half* gb = Bop + (size_t)(n0 + ldr) * NN + ldc8 * 8;

#define LOAD_CHUNK(kc, buf) do { \
    int _k0 = (kc) * 64; \
    uint32_t _as = sbase + (uint32_t)(buf) * 32768u + swz_ld; \
    uint32_t _bs = _as + 16384u; \
    _Pragma("unroll") for (int i = 0; i < 8; i++) { \
        cp16(_as + (uint32_t)i * 2048u, ga + (size_t)i * 16 * NN + _k0); \
        cp16(_bs + (uint32_t)i * 2048u, gb + (size_t)i * 16 * NN + _k0); \
    } \
    asm volatile("cp.async.commit_group;" ::: "memory"); \
} while (0)

    int wm = wid & 1, wn = wid >> 1;
    int lane4 = lid & 3, lgrp = lid >> 2;
    int t7 = lid & 7;
    uint32_t swzmask = (uint32_t)(t7 * 16);

    uint32_t a_rowbase = (uint32_t)((wm * 64 + t7 + (((lid >> 3) & 1) << 3)) * 128);
    uint32_t a_khoff   = (uint32_t)(((lid >> 4) & 1) * 16);
    uint32_t b_rowbase = (uint32_t)((wn * 64 + t7 + (((lid >> 4) & 1) << 3)) * 128);
    uint32_t b_khoff   = (uint32_t)(((lid >> 3) & 1) * 16);

    float acc[4][8][4];
#pragma unroll
    for (int mt = 0; mt < 4; mt++)
#pragma unroll
        for (int nt = 0; nt < 8; nt++)
#pragma unroll
            for (int c = 0; c < 4; c++) acc[mt][nt][c] = 0.f;

    LOAD_CHUNK(0, 0);
    LOAD_CHUNK(1, 1);

    int buf = 0, nbuf = 2;
    for (int kc = 0; kc < 32; kc++) {
        asm volatile("cp.async.wait_group 1;" ::: "memory");
        __syncthreads();

        if (kc + 2 < 32) LOAD_CHUNK(kc + 2, nbuf);
        else asm volatile("cp.async.commit_group;" ::: "memory");

        uint32_t ab = sbase + (uint32_t)buf * 32768u;
        uint32_t bb = ab + 16384u;
#pragma unroll
        for (int kk = 0; kk < 4; kk++) {
            uint32_t a[4][4], bfr[4][4];
            uint32_t a_k = ((uint32_t)(kk * 32) + a_khoff) ^ swzmask;
            uint32_t b_k = ((uint32_t)(kk * 32) + b_khoff) ^ swzmask;
#pragma unroll
            for (int mt = 0; mt < 4; mt++)
                ldmat4(a[mt], ab + a_rowbase + (uint32_t)(mt * 2048) + a_k);
#pragma unroll
            for (int bq = 0; bq < 4; bq++)
                ldmat4(bfr[bq], bb + b_rowbase + (uint32_t)(bq * 2048) + b_k);
#pragma unroll
            for (int mt = 0; mt < 4; mt++)
#pragma unroll
                for (int nt = 0; nt < 8; nt++)
                    mma16(acc[mt][nt], a[mt], &bfr[nt >> 1][(nt & 1) * 2]);
        }
        int t = buf; buf = (buf == 2) ? 0 : buf + 1; nbuf = t;
    }
#undef LOAD_CHUNK

    // ---- epilogue ----
    __syncthreads();
    float* st = (float*)smem;  // 128 x 128 staging, stride 129 (66 KB <= 96 KB)

    int row0 = m0 + wm * 64;
    int col0 = n0 + wn * 64 + lane4 * 2;
    int lr0  = wm * 64;
    int lc0  = wn * 64 + lane4 * 2;
#pragma unroll
    for (int mt = 0; mt < 4; mt++) {
#pragma unroll
        for (int nt = 0; nt < 8; nt++) {
            int r = row0 + mt * 16 + lgrp;
            int c = col0 + nt * 8;
            float v0 = alpha * acc[mt][nt][0];
            float v1 = alpha * acc[mt][nt][1];
            float v2 = alpha * acc[mt][nt][2];
            float v3 = alpha * acc[mt][nt][3];
            *(__half2*)&Ch[(size_t)r * ldcN + c]       = __floats2half2_rn(v0, v1);
            *(__half2*)&Ch[(size_t)(r + 8) * ldcN + c] = __floats2half2_rn(v2, v3);
            if (Ct) {
                int lr = lr0 + mt * 16 + lgrp;
                int lc = lc0 + nt * 8;
                st[lr * 129 + lc]           = v0;
                st[lr * 129 + lc + 1]       = v1;
                st[(lr + 8) * 129 + lc]     = v2;
                st[(lr + 8) * 129 + lc + 1] = v3;
            }
        }
    }
    if (Ct) {
        __syncthreads();
        for (int i = tid; i < 16384; i += 128) {
            int c = i >> 7, r = i & 127;
            Ct[(size_t)(n0 + c) * NN + m0 + r] = __float2half_rn(st[r * 129 + c]);
        }
    }
}

// ---------------- prepE: Et[d][m] = E[m][d] (fp32) ---------------------------
__global__ __launch_bounds__(256) void prepE_kernel(const float* __restrict__ E)
{
    int t = blockIdx.x * 256 + threadIdx.x;
    if (t < ED * NN) {
        int m = t & (NN - 1);
        int d = t >> 11;
        g_Et[(size_t)d * NN + m] = E[m * ED + d];
    }
}

// ---------------- A = softmax(relu(E E^T)): 8 rows/block, smem-cached Et -----
#define SUP_SMEM (ED * NN * 4)   // 80 KB dynamic
__global__ __launch_bounds__(256)
void supports_kernel(const float* __restrict__ E)
{
    extern __shared__ float Es[];          // [10][2048]
    __shared__ float red[256];
    int tid = threadIdx.x;

    for (int i = tid; i < ED * NN; i += 256) Es[i] = g_Et[i];
    __syncthreads();

    for (int rr = 0; rr < 8; rr++) {
        int n = blockIdx.x * 8 + rr;
        float en[ED];
#pragma unroll
        for (int d = 0; d < ED; d++) en[d] = __ldg(&E[n * ED + d]);

        float v[8], mx = 0.0f;
#pragma unroll
        for (int j = 0; j < 8; j++) {
            int m = j * 256 + tid;
            float dot = 0.f;
#pragma unroll
            for (int d = 0; d < ED; d++)
                dot += en[d] * Es[d * NN + m];
            v[j] = fmaxf(dot, 0.f);
            mx = fmaxf(mx, v[j]);
        }
        red[tid] = mx; __syncthreads();
        for (int s = 128; s > 0; s >>= 1) {
            if (tid < s) red[tid] = fmaxf(red[tid], red[tid + s]);
            __syncthreads();
        }
        mx = red[0]; __syncthreads();
        float sum = 0.f;
#pragma unroll
        for (int j = 0; j < 8; j++) { v[j] = __expf(v[j] - mx); sum += v[j]; }
        red[tid] = sum; __syncthreads();
        for (int s = 128; s > 0; s >>= 1) {
            if (tid < s) red[tid] += red[tid + s];
            __syncthreads();
        }
        float inv = 1.0f / red[0];
        __syncthreads();
#pragma unroll
        for (int j = 0; j < 8; j++)
            g_Ah[(size_t)n * NN + j * 256 + tid] = __float2half_rn(v[j] * inv);
    }
}

// ---------------- transpose_xTT: xTTh[b*64+c][n] = x[b][n][c] (critical) -----
__global__ __launch_bounds__(256) void transpose_xTT_kernel(const float* __restrict__ x)
{
    __shared__ float t[32][33];
    int tx = threadIdx.x, ty = threadIdx.y;
    int b = blockIdx.z;
    int n0 = blockIdx.x * 32, c0 = blockIdx.y * 32;
    const float* S = x + (size_t)b * NN * CC;
#pragma unroll
    for (int i = 0; i < 32; i += 8)
        t[ty + i][tx] = S[(size_t)(n0 + ty + i) * CC + c0 + tx];
    __syncthreads();
    __half* D = g_xTTh + (size_t)b * CC * NN;
#pragma unroll
    for (int i = 0; i < 32; i += 8)
        D[(size_t)(c0 + ty + i) * NN + n0 + tx] = __float2half_rn(t[tx][ty + i]);
}

// ---------------- conv_xh: xh[n][b*64+c] = fp16(x[b][n][c]) (lazy) -----------
__global__ __launch_bounds__(256) void conv_xh_kernel(const float* __restrict__ x)
{
    int t = blockIdx.x * 256 + threadIdx.x;
    int r = t & 1023;
    int n = t >> 10;
    int b = r >> 4, c4 = r & 15;
    float4 v = *(const float4*)&x[((size_t)b * NN + n) * CC + c4 * 4];
    __half2 h0 = __floats2half2_rn(v.x, v.y);
    __half2 h1 = __floats2half2_rn(v.z, v.w);
    *(uint2*)&g_xh[(size_t)n * BC + b * CC + c4 * 4] =
        make_uint2(*(uint32_t*)&h0, *(uint32_t*)&h1);
}

// ---------------- prepW: Wph[d][k][o][i] = fp16(Wp[d][k][i][o] - (k==0)*Wp[d][2][i][o])
__global__ __launch_bounds__(256) void prepW_kernel(const float* __restrict__ Wp)
{
    int t = blockIdx.x * 256 + threadIdx.x;
    int i  = t & 63;
    int o  = (t >> 6) & 63;
    int kd = t >> 12;
    int k  = kd % 3, d = kd / 3;
    float v = Wp[((size_t)kd * 64 + i) * 64 + o];
    if (k == 0) v -= Wp[((size_t)(d * 3 + 2) * 64 + i) * 64 + o];
    g_Wph[t] = __float2half_rn(v);
}

// ---------------- weights: WhT[n][k][o][i] = sum_d E[n,d] Wph[d][k][o][i] ----
__global__ __launch_bounds__(256) void weights_kernel(const float* __restrict__ E)
{
    size_t t = (size_t)blockIdx.x * 256 + threadIdx.x;
    int j8 = (int)(t % 1536);
    int n  = (int)(t / 1536);

    float acc[8];
#pragma unroll
    for (int q = 0; q < 8; q++) acc[q] = 0.f;

#pragma unroll
    for (int d = 0; d < ED; d++) {
        float e = __ldg(&E[n * ED + d]);
        uint4 w = *(const uint4*)&g_Wph[(size_t)d * 12288 + (size_t)j8 * 8];
        const __half2* h = (const __half2*)&w;
#pragma unroll
        for (int q = 0; q < 4; q++) {
            float2 f = __half22float2(h[q]);
            acc[q * 2]     += e * f.x;
            acc[q * 2 + 1] += e * f.y;
        }
    }
    uint4 outw;
    __half2* ho = (__half2*)&outw;
#pragma unroll
    for (int q = 0; q < 4; q++)
        ho[q] = __floats2half2_rn(acc[q * 2], acc[q * 2 + 1]);
    *(uint4*)&g_WhT[(size_t)n * 12288 + (size_t)j8 * 8] = outw;
}

// ---------------- final_tc: out[:,n,:] = [x|Xg1|Xg2p] @ WhT_n + bias ---------
#define FT_SMEM (49152 + 256)
__global__ __launch_bounds__(128)
void final_tc(const float* __restrict__ E, const float* __restrict__ bp,
              float* __restrict__ out, int n0off)
{
    extern __shared__ char sm[];
    uint32_t sb = smem_u32(sm);
    float* biass = (float*)(sm + 49152);
    int n = blockIdx.x + n0off, tid = threadIdx.x, wid = tid >> 5, lid = tid & 31;

    if (tid < 64) {
        float b = 0.f;
#pragma unroll
        for (int d = 0; d < ED; d++) b += __ldg(&E[n * ED + d]) * __ldg(&bp[d * CC + tid]);
        biass[tid] = b;
    }

    const __half* srcs[3] = { g_xh   + (size_t)n * BC,
                              g_Xg1h + (size_t)n * BC,
                              g_Xg2ph+ (size_t)n * BC };
#pragma unroll
    for (int s = 0; s < 3; s++) {
        const char* g = (const char*)srcs[s];
        for (int ch = tid; ch < 512; ch += 128) {
            int r = ch >> 3, c16 = ch & 7;
            uint32_t dst = sb + (uint32_t)(s * 8192)
                         + (uint32_t)(r * 128 + ((c16 * 16) ^ ((r & 7) * 16)));
            cp16(dst, g + r * 128 + c16 * 16);
        }
    }
    {
        const char* g = (const char*)(g_WhT + (size_t)n * 12288);
        for (int ch = tid; ch < 1536; ch += 128) {
            int r = ch >> 3, c16 = ch & 7;
            uint32_t dst = sb + 24576u
                         + (uint32_t)(r * 128 + ((c16 * 16) ^ ((r & 7) * 16)));
            cp16(dst, g + r * 128 + c16 * 16);
        }
    }
    asm volatile("cp.async.commit_group;" ::: "memory");
    asm volatile("cp.async.wait_group 0;" ::: "memory");
    __syncthreads();

    int t7 = lid & 7, lane4 = lid & 3, lgrp = lid >> 2;
    uint32_t swzmask = (uint32_t)(t7 * 16);
    uint32_t a_rowbase = (uint32_t)((wid * 16 + t7 + (((lid >> 3) & 1) << 3)) * 128);
    uint32_t a_khoff   = (uint32_t)(((lid >> 4) & 1) * 16);
    uint32_t b_rowbase = (uint32_t)((t7 + (((lid >> 4) & 1) << 3)) * 128);
    uint32_t b_khoff   = (uint32_t)(((lid >> 3) & 1) * 16);

    float acc[8][4];
#pragma unroll
    for (int j = 0; j < 8; j++)
#pragma unroll
        for (int c = 0; c < 4; c++) acc[j][c] = 0.f;

#pragma unroll
    for (int s = 0; s < 3; s++) {
#pragma unroll
        for (int kk = 0; kk < 4; kk++) {
            uint32_t a[4], bfr[4][4];
            uint32_t ak = ((uint32_t)(kk * 32) + a_khoff) ^ swzmask;
            uint32_t bk = ((uint32_t)(kk * 32) + b_khoff) ^ swzmask;
            ldmat4(a, sb + (uint32_t)(s * 8192) + a_rowbase + ak);
#pragma unroll
            for (int q = 0; q < 4; q++)
                ldmat4(bfr[q], sb + 24576u + (uint32_t)(s * 8192)
                               + b_rowbase + (uint32_t)(q * 2048) + bk);
#pragma unroll
            for (int j = 0; j < 8; j++)
                mma16(acc[j], a, &bfr[j >> 1][(j & 1) * 2]);
        }
    }

    int brow = wid * 16 + lgrp;
#pragma unroll
    for (int j = 0; j < 8; j++) {
        int o = j * 8 + lane4 * 2;
        float b0 = biass[o], b1 = biass[o + 1];
        *(float2*)&out[((size_t)brow * NN + n) * CC + o] =
            make_float2(acc[j][0] + b0, acc[j][1] + b1);
        *(float2*)&out[((size_t)(brow + 8) * NN + n) * CC + o] =
            make_float2(acc[j][2] + b0, acc[j][3] + b1);
    }
}

// ---------------- launch ----------------------------------------------------
#define GEMM_SMEM 98304

extern "C" void kernel_launch(void* const* d_in, const int* in_sizes, int n_in,
                              void* d_out, int out_size)
{
    const float* x  = (const float*)d_in[0];
    const float* E  = (const float*)d_in[1];
    const float* Wp = (const float*)d_in[2];
    const float* bp = (const float*)d_in[3];
    float* out = (float*)d_out;

    __half *pAh, *pxTTh, *pXg1h, *pXg1T, *pXg2ph;
    cudaGetSymbolAddress((void**)&pAh,    g_Ah);
    cudaGetSymbolAddress((void**)&pxTTh,  g_xTTh);
    cudaGetSymbolAddress((void**)&pXg1h,  g_Xg1h);
    cudaGetSymbolAddress((void**)&pXg1T,  g_Xg1T);
    cudaGetSymbolAddress((void**)&pXg2ph, g_Xg2ph);

    static bool init_done = false;
    static cudaStream_t s1, s2;
    static cudaEvent_t e0, e1, e2, eG2a, eFa;
    if (!init_done) {
        cudaFuncSetAttribute(gemm_mma, cudaFuncAttributeMaxDynamicSharedMemorySize, GEMM_SMEM);
        cudaFuncSetAttribute(final_tc, cudaFuncAttributeMaxDynamicSharedMemorySize, FT_SMEM);
        cudaFuncSetAttribute(supports_kernel, cudaFuncAttributeMaxDynamicSharedMemorySize, SUP_SMEM);
        cudaStreamCreateWithFlags(&s1, cudaStreamNonBlocking);
        cudaStreamCreateWithFlags(&s2, cudaStreamNonBlocking);
        cudaEventCreateWithFlags(&e0,   cudaEventDisableTiming);
        cudaEventCreateWithFlags(&e1,   cudaEventDisableTiming);
        cudaEventCreateWithFlags(&e2,   cudaEventDisableTiming);
        cudaEventCreateWithFlags(&eG2a, cudaEventDisableTiming);
        cudaEventCreateWithFlags(&eFa,  cudaEventDisableTiming);
        init_done = true;
    }

    // fork side streams from the capture-origin (default) stream
    cudaEventRecord(e0, 0);
    cudaStreamWaitEvent(s1, e0, 0);
    cudaStreamWaitEvent(s2, e0, 0);

    // s1: CRITICAL x transpose only (xTTh) — gates GEMM1
    transpose_xTT_kernel<<<dim3(64, 2, 64), dim3(32, 8), 0, s1>>>(x);
    cudaEventRecord(e1, s1);

    // s2: lazy conversions (gate final_tc only)
    conv_xh_kernel<<<(NN * BC / 4) / 256, 256, 0, s2>>>(x);
    prepW_kernel<<<480, 256, 0, s2>>>(Wp);
    weights_kernel<<<(NN * 1536) / 256, 256, 0, s2>>>(E);
    cudaEventRecord(e2, s2);

    // main: E transpose (fp32) + adjacency (smem-cached Et, 8 rows/block)
    prepE_kernel<<<80, 256>>>(E);
    supports_kernel<<<256, 256, SUP_SMEM>>>(E);

    // join s1 before GEMM1
    cudaStreamWaitEvent(0, e1, 0);

    // GEMM1: Xg1h = fp16(A @ xT)  (+ fused fp16 transposed copy Xg1T)
    gemm_mma<<<dim3(BC / 128, NN / 128), 128, GEMM_SMEM>>>(pAh, pxTTh, pXg1h, BC, 1.0f, pXg1T, 0);

    // GEMM2a: Xg2ph rows 0..1023
    gemm_mma<<<dim3(BC / 128, 8), 128, GEMM_SMEM>>>(pAh, pXg1T, pXg2ph, BC, 2.0f, nullptr, 0);
    cudaEventRecord(eG2a, 0);

    // s2: final_tc nodes 0..1023, overlapping GEMM2b
    cudaStreamWaitEvent(s2, eG2a, 0);
    final_tc<<<1024, 128, FT_SMEM, s2>>>(E, bp, out, 0);
    cudaEventRecord(eFa, s2);

    // main: GEMM2b rows 1024..2047
    gemm_mma<<<dim3(BC / 128, 8), 128, GEMM_SMEM>>>(pAh, pXg1T, pXg2ph, BC, 2.0f, nullptr, 8);

    // main: final_tc nodes 1024..2047 (join s2's weight chain first)
    cudaStreamWaitEvent(0, e2, 0);
    final_tc<<<1024, 128, FT_SMEM>>>(E, bp, out, 1024);

    // join s2's first final half back
    cudaStreamWaitEvent(0, eFa, 0);
}

// round 17
// speedup vs baseline: 1.0159x; 1.0159x over previous
#include <cuda_runtime.h>
#include <cuda_fp16.h>
#include <cstdint>

// Problem constants
#define NN   2048
#define BB   64
#define CC   64
#define ED   10
#define BC   4096
#define KCH  3

// ---------------- scratch ------------------------------------------------------
__device__ float  g_Et   [(size_t)ED * NN];   // E^T fp32 [d][m]
__device__ __half g_Ah   [(size_t)NN * NN];   // softmax(relu(E E^T)), fp16
__device__ __half g_xTTh [(size_t)BC * NN];   // xTT[b*64+c][n], fp16 (GEMM1 B operand)
__device__ __half g_xh   [(size_t)NN * BC];   // x as [n][b*64+c], fp16 (final_tc seg0)
__device__ __half g_Xg1h [(size_t)NN * BC];   // A @ xT, fp16 [n][bc]
__device__ __half g_Xg1T [(size_t)BC * NN];   // Xg1^T fp16 (GEMM2 B operand)
__device__ __half g_Xg2ph[(size_t)NN * BC];   // 2 A @ Xg1, fp16 [n][bc]
__device__ __half g_Wph  [(size_t)ED * KCH * CC * CC]; // Wp [d][k][o][i], slot0 folded
__device__ __half g_WhT  [(size_t)NN * KCH * CC * CC]; // per-node W^T [n][k][o][i]

// ---------------- helpers ------------------------------------------------
__device__ __forceinline__ uint32_t smem_u32(const void* p) {
    uint32_t a;
    asm("{ .reg .u64 t; cvta.to.shared.u64 t, %1; cvt.u32.u64 %0, t; }" : "=r"(a) : "l"(p));
    return a;
}
__device__ __forceinline__ void cp16(uint32_t dst, const void* src) {
    asm volatile("cp.async.cg.shared.global [%0], [%1], 16;" :: "r"(dst), "l"(src) : "memory");
}
__device__ __forceinline__ void mma16(float* d, const uint32_t* a, const uint32_t* b) {
    asm volatile("mma.sync.aligned.m16n8k16.row.col.f32.f16.f16.f32 "
        "{%0,%1,%2,%3}, {%4,%5,%6,%7}, {%8,%9}, {%0,%1,%2,%3};"
        : "+f"(d[0]), "+f"(d[1]), "+f"(d[2]), "+f"(d[3])
        : "r"(a[0]), "r"(a[1]), "r"(a[2]), "r"(a[3]), "r"(b[0]), "r"(b[1]));
}
__device__ __forceinline__ void ldmat4(uint32_t* r, uint32_t addr) {
    asm volatile("ldmatrix.sync.aligned.m8n8.x4.shared.b16 {%0,%1,%2,%3}, [%4];"
        : "=r"(r[0]), "=r"(r[1]), "=r"(r[2]), "=r"(r[3]) : "r"(addr));
}

// ---------------- fp16 mma.sync GEMM: Ch = fp16(alpha * Aop @ Bop^T) ---------
// CTA tile 128x128, 4 warps x (64x64) warp tiles, K-chunk 64, 3-stage cp.async
// pipeline, ldmatrix fragment feeds.  blockDim = 128.
// by0: M-block offset.  If Ct != null, also writes fp16 transposed tile to Ct.
__global__ __launch_bounds__(128, 2)
void gemm_mma(const __half* __restrict__ Aop, const __half* __restrict__ Bop,
              __half* __restrict__ Ch, int ldcN, float alpha,
              __half* __restrict__ Ct, int by0)
{
    extern __shared__ char smem[];
    uint32_t sbase = smem_u32(smem);

    int tid = threadIdx.x, wid = tid >> 5, lid = tid & 31;
    int m0 = (blockIdx.y + by0) * 128, n0 = blockIdx.x * 128;

    int ldr = tid >> 3, ldc8 = tid & 7;
    uint32_t swz_ld = (uint32_t)(ldr * 128 + ((ldc8 * 16) ^ ((ldr & 7) * 16)));
    const __half* ga = Aop + (size_t)(m0 + ldr) * NN + ldc8 * 8;
    const __half* gb = Bop + (size_t)(n0 + ldr) * NN + ldc8 * 8;

#define LOAD_CHUNK(kc, buf) do { \
    int _k0 = (kc) * 64; \
    uint32_t _as = sbase + (uint32_t)(buf) * 32768u + swz_ld; \
    uint32_t _bs = _as + 16384u; \
    _Pragma("unroll") for (int i = 0; i < 8; i++) { \
        cp16(_as + (uint32_t)i * 2048u, ga + (size_t)i * 16 * NN + _k0); \
        cp16(_bs + (uint32_t)i * 2048u, gb + (size_t)i * 16 * NN + _k0); \
    } \
    asm volatile("cp.async.commit_group;" ::: "memory"); \
} while (0)

    int wm = wid & 1, wn = wid >> 1;
    int lane4 = lid & 3, lgrp = lid >> 2;
    int t7 = lid & 7;
    uint32_t swzmask = (uint32_t)(t7 * 16);

    uint32_t a_rowbase = (uint32_t)((wm * 64 + t7 + (((lid >> 3) & 1) << 3)) * 128);
    uint32_t a_khoff   = (uint32_t)(((lid >> 4) & 1) * 16);
    uint32_t b_rowbase = (uint32_t)((wn * 64 + t7 + (((lid >> 4) & 1) << 3)) * 128);
    uint32_t b_khoff   = (uint32_t)(((lid >> 3) & 1) * 16);

    float acc[4][8][4];
#pragma unroll
    for (int mt = 0; mt < 4; mt++)
#pragma unroll
        for (int nt = 0; nt < 8; nt++)
#pragma unroll
            for (int c = 0; c < 4; c++) acc[mt][nt][c] = 0.f;

    LOAD_CHUNK(0, 0);
    LOAD_CHUNK(1, 1);

    int buf = 0, nbuf = 2;
    for (int kc = 0; kc < 32; kc++) {
        asm volatile("cp.async.wait_group 1;" ::: "memory");
        __syncthreads();

        if (kc + 2 < 32) LOAD_CHUNK(kc + 2, nbuf);
        else asm volatile("cp.async.commit_group;" ::: "memory");

        uint32_t ab = sbase + (uint32_t)buf * 32768u;
        uint32_t bb = ab + 16384u;
#pragma unroll
        for (int kk = 0; kk < 4; kk++) {
            uint32_t a[4][4], bfr[4][4];
            uint32_t a_k = ((uint32_t)(kk * 32) + a_khoff) ^ swzmask;
            uint32_t b_k = ((uint32_t)(kk * 32) + b_khoff) ^ swzmask;
#pragma unroll
            for (int mt = 0; mt < 4; mt++)
                ldmat4(a[mt], ab + a_rowbase + (uint32_t)(mt * 2048) + a_k);
#pragma unroll
            for (int bq = 0; bq < 4; bq++)
                ldmat4(bfr[bq], bb + b_rowbase + (uint32_t)(bq * 2048) + b_k);
#pragma unroll
            for (int mt = 0; mt < 4; mt++)
#pragma unroll
                for (int nt = 0; nt < 8; nt++)
                    mma16(acc[mt][nt], a[mt], &bfr[nt >> 1][(nt & 1) * 2]);
        }
        int t = buf; buf = (buf == 2) ? 0 : buf + 1; nbuf = t;
    }
#undef LOAD_CHUNK

    // ---- epilogue ----
    __syncthreads();
    float* st = (float*)smem;  // 128 x 128 staging, stride 129 (66 KB <= 96 KB)

    int row0 = m0 + wm * 64;
    int col0 = n0 + wn * 64 + lane4 * 2;
    int lr0  = wm * 64;
    int lc0  = wn * 64 + lane4 * 2;
#pragma unroll
    for (int mt = 0; mt < 4; mt++) {
#pragma unroll
        for (int nt = 0; nt < 8; nt++) {
            int r = row0 + mt * 16 + lgrp;
            int c = col0 + nt * 8;
            float v0 = alpha * acc[mt][nt][0];
            float v1 = alpha * acc[mt][nt][1];
            float v2 = alpha * acc[mt][nt][2];
            float v3 = alpha * acc[mt][nt][3];
            *(__half2*)&Ch[(size_t)r * ldcN + c]       = __floats2half2_rn(v0, v1);
            *(__half2*)&Ch[(size_t)(r + 8) * ldcN + c] = __floats2half2_rn(v2, v3);
            if (Ct) {
                int lr = lr0 + mt * 16 + lgrp;
                int lc = lc0 + nt * 8;
                st[lr * 129 + lc]           = v0;
                st[lr * 129 + lc + 1]       = v1;
                st[(lr + 8) * 129 + lc]     = v2;
                st[(lr + 8) * 129 + lc + 1] = v3;
            }
        }
    }
    if (Ct) {
        __syncthreads();
        for (int i = tid; i < 16384; i += 128) {
            int c = i >> 7, r = i & 127;
            Ct[(size_t)(n0 + c) * NN + m0 + r] = __float2half_rn(st[r * 129 + c]);
        }
    }
}

// ---------------- prepE: Et[d][m] = E[m][d] (fp32) ---------------------------
__global__ __launch_bounds__(256) void prepE_kernel(const float* __restrict__ E)
{
    int t = blockIdx.x * 256 + threadIdx.x;
    if (t < ED * NN) {
        int m = t & (NN - 1);
        int d = t >> 11;
        g_Et[(size_t)d * NN + m] = E[m * ED + d];
    }
}

// ---------------- A = softmax(relu(E E^T)), coalesced fp32 reads, __expf -----
__global__ __launch_bounds__(256) void supports_kernel(const float* __restrict__ E)
{
    int n = blockIdx.x, tid = threadIdx.x;
    float en[ED];
#pragma unroll
    for (int d = 0; d < ED; d++) en[d] = E[n * ED + d];

    float v[8], mx = 0.0f;
#pragma unroll
    for (int j = 0; j < 8; j++) {
        int m = j * 256 + tid;
        float dot = 0.f;
#pragma unroll
        for (int d = 0; d < ED; d++)
            dot += en[d] * __ldg(&g_Et[(size_t)d * NN + m]);
        v[j] = fmaxf(dot, 0.f);
        mx = fmaxf(mx, v[j]);
    }
    __shared__ float red[256];
    red[tid] = mx; __syncthreads();
    for (int s = 128; s > 0; s >>= 1) {
        if (tid < s) red[tid] = fmaxf(red[tid], red[tid + s]);
        __syncthreads();
    }
    mx = red[0]; __syncthreads();
    float sum = 0.f;
#pragma unroll
    for (int j = 0; j < 8; j++) { v[j] = __expf(v[j] - mx); sum += v[j]; }
    red[tid] = sum; __syncthreads();
    for (int s = 128; s > 0; s >>= 1) {
        if (tid < s) red[tid] += red[tid + s];
        __syncthreads();
    }
    float inv = 1.0f / red[0];
#pragma unroll
    for (int j = 0; j < 8; j++)
        g_Ah[(size_t)n * NN + j * 256 + tid] = __float2half_rn(v[j] * inv);
}

// ---------------- transpose_xTT: 64x64 tiles, 128B fp16 writes ---------------
__global__ __launch_bounds__(256) void transpose_xTT_kernel(const float* __restrict__ x)
{
    __shared__ float ts[64][65];           // [c][n_local]
    int tid = threadIdx.x;
    int b = blockIdx.z, n0 = blockIdx.x * 64;

    // read 64 n-rows x 64 c floats (float4, coalesced)
#pragma unroll
    for (int it = 0; it < 4; it++) {
        int idx = tid + it * 256;          // 0..1023
        int nl = idx >> 4, c4 = idx & 15;
        float4 v = *(const float4*)&x[((size_t)b * NN + n0 + nl) * CC + c4 * 4];
        ts[c4 * 4 + 0][nl] = v.x;
        ts[c4 * 4 + 1][nl] = v.y;
        ts[c4 * 4 + 2][nl] = v.z;
        ts[c4 * 4 + 3][nl] = v.w;
    }
    __syncthreads();

    // write 64 c-rows x 64 n halves (half2, 128B per warp, coalesced)
#pragma unroll
    for (int it = 0; it < 8; it++) {
        int idx = tid + it * 256;          // 0..2047
        int c = idx >> 5, n2 = idx & 31;
        __half2 h = __floats2half2_rn(ts[c][n2 * 2], ts[c][n2 * 2 + 1]);
        *(__half2*)&g_xTTh[((size_t)b * CC + c) * NN + n0 + n2 * 2] = h;
    }
}

// ---------------- conv_xh: xh[n][b*64+c] = fp16(x[b][n][c]) (lazy) -----------
__global__ __launch_bounds__(256) void conv_xh_kernel(const float* __restrict__ x)
{
    int t = blockIdx.x * 256 + threadIdx.x;
    int r = t & 1023;
    int n = t >> 10;
    int b = r >> 4, c4 = r & 15;
    float4 v = *(const float4*)&x[((size_t)b * NN + n) * CC + c4 * 4];
    __half2 h0 = __floats2half2_rn(v.x, v.y);
    __half2 h1 = __floats2half2_rn(v.z, v.w);
    *(uint2*)&g_xh[(size_t)n * BC + b * CC + c4 * 4] =
        make_uint2(*(uint32_t*)&h0, *(uint32_t*)&h1);
}

// ---------------- prepW: Wph[d][k][o][i] = fp16(Wp[d][k][i][o] - (k==0)*Wp[d][2][i][o])
__global__ __launch_bounds__(256) void prepW_kernel(const float* __restrict__ Wp)
{
    int t = blockIdx.x * 256 + threadIdx.x;
    int i  = t & 63;
    int o  = (t >> 6) & 63;
    int kd = t >> 12;
    int k  = kd % 3, d = kd / 3;
    float v = Wp[((size_t)kd * 64 + i) * 64 + o];
    if (k == 0) v -= Wp[((size_t)(d * 3 + 2) * 64 + i) * 64 + o];
    g_Wph[t] = __float2half_rn(v);
}

// ---------------- weights: WhT[n][k][o][i] = sum_d E[n,d] Wph[d][k][o][i] ----
__global__ __launch_bounds__(256) void weights_kernel(const float* __restrict__ E)
{
    size_t t = (size_t)blockIdx.x * 256 + threadIdx.x;
    int j8 = (int)(t % 1536);
    int n  = (int)(t / 1536);

    float acc[8];
#pragma unroll
    for (int q = 0; q < 8; q++) acc[q] = 0.f;

#pragma unroll
    for (int d = 0; d < ED; d++) {
        float e = __ldg(&E[n * ED + d]);
        uint4 w = *(const uint4*)&g_Wph[(size_t)d * 12288 + (size_t)j8 * 8];
        const __half2* h = (const __half2*)&w;
#pragma unroll
        for (int q = 0; q < 4; q++) {
            float2 f = __half22float2(h[q]);
            acc[q * 2]     += e * f.x;
            acc[q * 2 + 1] += e * f.y;
        }
    }
    uint4 outw;
    __half2* ho = (__half2*)&outw;
#pragma unroll
    for (int q = 0; q < 4; q++)
        ho[q] = __floats2half2_rn(acc[q * 2], acc[q * 2 + 1]);
    *(uint4*)&g_WhT[(size_t)n * 12288 + (size_t)j8 * 8] = outw;
}

// ---------------- final_tc: out[:,n,:] = [x|Xg1|Xg2p] @ WhT_n + bias ---------
#define FT_SMEM (49152 + 256)
__global__ __launch_bounds__(128)
void final_tc(const float* __restrict__ E, const float* __restrict__ bp,
              float* __restrict__ out, int n0off)
{
    extern __shared__ char sm[];
    uint32_t sb = smem_u32(sm);
    float* biass = (float*)(sm + 49152);
    int n = blockIdx.x + n0off, tid = threadIdx.x, wid = tid >> 5, lid = tid & 31;

    if (tid < 64) {
        float b = 0.f;
#pragma unroll
        for (int d = 0; d < ED; d++) b += __ldg(&E[n * ED + d]) * __ldg(&bp[d * CC + tid]);
        biass[tid] = b;
    }

    const __half* srcs[3] = { g_xh   + (size_t)n * BC,
                              g_Xg1h + (size_t)n * BC,
                              g_Xg2ph+ (size_t)n * BC };
#pragma unroll
    for (int s = 0; s < 3; s++) {
        const char* g = (const char*)srcs[s];
        for (int ch = tid; ch < 512; ch += 128) {
            int r = ch >> 3, c16 = ch & 7;
            uint32_t dst = sb + (uint32_t)(s * 8192)
                         + (uint32_t)(r * 128 + ((c16 * 16) ^ ((r & 7) * 16)));
            cp16(dst, g + r * 128 + c16 * 16);
        }
    }
    {
        const char* g = (const char*)(g_WhT + (size_t)n * 12288);
        for (int ch = tid; ch < 1536; ch += 128) {
            int r = ch >> 3, c16 = ch & 7;
            uint32_t dst = sb + 24576u
                         + (uint32_t)(r * 128 + ((c16 * 16) ^ ((r & 7) * 16)));
            cp16(dst, g + r * 128 + c16 * 16);
        }
    }
    asm volatile("cp.async.commit_group;" ::: "memory");
    asm volatile("cp.async.wait_group 0;" ::: "memory");
    __syncthreads();

    int t7 = lid & 7, lane4 = lid & 3, lgrp = lid >> 2;
    uint32_t swzmask = (uint32_t)(t7 * 16);
    uint32_t a_rowbase = (uint32_t)((wid * 16 + t7 + (((lid >> 3) & 1) << 3)) * 128);
    uint32_t a_khoff   = (uint32_t)(((lid >> 4) & 1) * 16);
    uint32_t b_rowbase = (uint32_t)((t7 + (((lid >> 4) & 1) << 3)) * 128);
    uint32_t b_khoff   = (uint32_t)(((lid >> 3) & 1) * 16);

    float acc[8][4];
#pragma unroll
    for (int j = 0; j < 8; j++)
#pragma unroll
        for (int c = 0; c < 4; c++) acc[j][c] = 0.f;

#pragma unroll
    for (int s = 0; s < 3; s++) {
#pragma unroll
        for (int kk = 0; kk < 4; kk++) {
            uint32_t a[4], bfr[4][4];
            uint32_t ak = ((uint32_t)(kk * 32) + a_khoff) ^ swzmask;
            uint32_t bk = ((uint32_t)(kk * 32) + b_khoff) ^ swzmask;
            ldmat4(a, sb + (uint32_t)(s * 8192) + a_rowbase + ak);
#pragma unroll
            for (int q = 0; q < 4; q++)
                ldmat4(bfr[q], sb + 24576u + (uint32_t)(s * 8192)
                               + b_rowbase + (uint32_t)(q * 2048) + bk);
#pragma unroll
            for (int j = 0; j < 8; j++)
                mma16(acc[j], a, &bfr[j >> 1][(j & 1) * 2]);
        }
    }

    int brow = wid * 16 + lgrp;
#pragma unroll
    for (int j = 0; j < 8; j++) {
        int o = j * 8 + lane4 * 2;
        float b0 = biass[o], b1 = biass[o + 1];
        *(float2*)&out[((size_t)brow * NN + n) * CC + o] =
            make_float2(acc[j][0] + b0, acc[j][1] + b1);
        *(float2*)&out[((size_t)(brow + 8) * NN + n) * CC + o] =
            make_float2(acc[j][2] + b0, acc[j][3] + b1);
    }
}

// ---------------- launch ----------------------------------------------------
#define GEMM_SMEM 98304

extern "C" void kernel_launch(void* const* d_in, const int* in_sizes, int n_in,
                              void* d_out, int out_size)
{
    const float* x  = (const float*)d_in[0];
    const float* E  = (const float*)d_in[1];
    const float* Wp = (const float*)d_in[2];
    const float* bp = (const float*)d_in[3];
    float* out = (float*)d_out;

    __half *pAh, *pxTTh, *pXg1h, *pXg1T, *pXg2ph;
    cudaGetSymbolAddress((void**)&pAh,    g_Ah);
    cudaGetSymbolAddress((void**)&pxTTh,  g_xTTh);
    cudaGetSymbolAddress((void**)&pXg1h,  g_Xg1h);
    cudaGetSymbolAddress((void**)&pXg1T,  g_Xg1T);
    cudaGetSymbolAddress((void**)&pXg2ph, g_Xg2ph);

    static bool init_done = false;
    static cudaStream_t s1, s2;
    static cudaEvent_t e0, e1, e2, eG2a, eFa;
    if (!init_done) {
        cudaFuncSetAttribute(gemm_mma, cudaFuncAttributeMaxDynamicSharedMemorySize, GEMM_SMEM);
        cudaFuncSetAttribute(final_tc, cudaFuncAttributeMaxDynamicSharedMemorySize, FT_SMEM);
        cudaStreamCreateWithFlags(&s1, cudaStreamNonBlocking);
        cudaStreamCreateWithFlags(&s2, cudaStreamNonBlocking);
        cudaEventCreateWithFlags(&e0,   cudaEventDisableTiming);
        cudaEventCreateWithFlags(&e1,   cudaEventDisableTiming);
        cudaEventCreateWithFlags(&e2,   cudaEventDisableTiming);
        cudaEventCreateWithFlags(&eG2a, cudaEventDisableTiming);
        cudaEventCreateWithFlags(&eFa,  cudaEventDisableTiming);
        init_done = true;
    }

    // fork side streams from the capture-origin (default) stream
    cudaEventRecord(e0, 0);
    cudaStreamWaitEvent(s1, e0, 0);
    cudaStreamWaitEvent(s2, e0, 0);

    // s1: CRITICAL x transpose only (xTTh, 64x64 tiles, 128B writes)
    transpose_xTT_kernel<<<dim3(32, 1, 64), 256, 0, s1>>>(x);
    cudaEventRecord(e1, s1);

    // s2: lazy conversions (gate final_tc only)
    conv_xh_kernel<<<(NN * BC / 4) / 256, 256, 0, s2>>>(x);
    prepW_kernel<<<480, 256, 0, s2>>>(Wp);
    weights_kernel<<<(NN * 1536) / 256, 256, 0, s2>>>(E);
    cudaEventRecord(e2, s2);

    // main: E transpose (fp32) + adjacency (coalesced global, __expf)
    prepE_kernel<<<80, 256>>>(E);
    supports_kernel<<<NN, 256>>>(E);

    // join s1 before GEMM1
    cudaStreamWaitEvent(0, e1, 0);

    // GEMM1: Xg1h = fp16(A @ xT)  (+ fused fp16 transposed copy Xg1T)
    gemm_mma<<<dim3(BC / 128, NN / 128), 128, GEMM_SMEM>>>(pAh, pxTTh, pXg1h, BC, 1.0f, pXg1T, 0);

    // GEMM2a: Xg2ph rows 0..1023
    gemm_mma<<<dim3(BC / 128, 8), 128, GEMM_SMEM>>>(pAh, pXg1T, pXg2ph, BC, 2.0f, nullptr, 0);
    cudaEventRecord(eG2a, 0);

    // s2: final_tc nodes 0..1023, overlapping GEMM2b
    cudaStreamWaitEvent(s2, eG2a, 0);
    final_tc<<<1024, 128, FT_SMEM, s2>>>(E, bp, out, 0);
    cudaEventRecord(eFa, s2);

    // main: GEMM2b rows 1024..2047
    gemm_mma<<<dim3(BC / 128, 8), 128, GEMM_SMEM>>>(pAh, pXg1T, pXg2ph, BC, 2.0f, nullptr, 8);

    // main: final_tc nodes 1024..2047 (join s2's weight chain first)
    cudaStreamWaitEvent(0, e2, 0);
    final_tc<<<1024, 128, FT_SMEM>>>(E, bp, out, 1024);

    // join s2's first final half back
    cudaStreamWaitEvent(0, eFa, 0);
}